// round 16
// baseline (speedup 1.0000x reference)
#include <cuda_runtime.h>
#include <cuda_fp16.h>
#include <stdint.h>
#include <math.h>

#define NTOK  8192
#define HID   1024
#define INTER 4096
#define NEXP  8
#define NEXPC 7
#define CAP   1024

#define STAGES      3
#define STAGE_BYTES 32768           /* A 16KB (128 rows) + B 16KB (128 rows) */
#define GEMM_SMEM   (STAGES * STAGE_BYTES + 1024)

/* ---------------- device scratch (static: no allocations allowed) -------- */
__device__ int2   g_e01[NTOK];
__device__ float2 g_w01[NTOK];
__device__ float  g_wn[NTOK];
__device__ int    g_list[NEXPC * CAP];
__device__ float  g_wl[NEXPC * CAP];
__device__ __half g_xh[(size_t)NTOK * HID];             /* fp16 x            */
__device__ __half g_Wih[(size_t)NEXPC * INTER * HID];   /* Wi^T [e][n][k]    */
__device__ __half g_Woh[(size_t)NEXPC * HID * INTER];   /* Wo^T [e][n][k]    */
__device__ __half g_Hh[(size_t)NEXPC * CAP * INTER];    /* fp16 H            */

struct __align__(8) H4 { __half2 a, b; };

/* ---------------- helpers -------------------------------------------------- */
__device__ __forceinline__ unsigned smem_u32(const void* p) {
    return (unsigned)__cvta_generic_to_shared(p);
}
__device__ __forceinline__ unsigned sw128(unsigned x) { return x ^ ((x >> 3) & 0x70u); }

__device__ __forceinline__ void cp_async16(unsigned sa, const void* g) {
    asm volatile("cp.async.cg.shared.global [%0], [%1], 16;" :: "r"(sa), "l"(g));
}
__device__ __forceinline__ void cp_commit() {
    asm volatile("cp.async.commit_group;");
}
__device__ __forceinline__ void cp_wait_1() {
    asm volatile("cp.async.wait_group 1;");
}

__device__ __forceinline__ void ldm_x4(unsigned* r, unsigned addr) {
    asm volatile("ldmatrix.sync.aligned.m8n8.x4.shared.b16 {%0, %1, %2, %3}, [%4];"
                 : "=r"(r[0]), "=r"(r[1]), "=r"(r[2]), "=r"(r[3]) : "r"(addr));
}
__device__ __forceinline__ void mma16816(float* d, const unsigned* a,
                                         unsigned b0, unsigned b1) {
    asm volatile(
        "mma.sync.aligned.m16n8k16.row.col.f32.f16.f16.f32 "
        "{%0, %1, %2, %3}, {%4, %5, %6, %7}, {%8, %9}, {%0, %1, %2, %3};"
        : "+f"(d[0]), "+f"(d[1]), "+f"(d[2]), "+f"(d[3])
        : "r"(a[0]), "r"(a[1]), "r"(a[2]), "r"(a[3]), "r"(b0), "r"(b1));
}

/* ---------------- router: logits -> softmax -> top2 ---------------------- */
__global__ __launch_bounds__(256) void router_kernel(const float* __restrict__ x,
                                                     const float* __restrict__ rw,
                                                     const float* __restrict__ rb)
{
    __shared__ __align__(16) float s_rw[NEXP * HID];
    int tid = threadIdx.x;
    for (int i = tid * 4; i < NEXP * HID; i += 256 * 4)
        *(float4*)&s_rw[i] = *(const float4*)&rw[i];
    __syncthreads();

    int lane = tid & 31;
    int warp = tid >> 5;
    int t = blockIdx.x * 8 + warp;

    float acc[NEXP];
#pragma unroll
    for (int e = 0; e < NEXP; e++) acc[e] = 0.f;

    const float4* xr = (const float4*)(x + (size_t)t * HID);
#pragma unroll
    for (int i = 0; i < 8; i++) {
        int k4 = lane + i * 32;
        float4 xv = xr[k4];
#pragma unroll
        for (int e = 0; e < NEXP; e++) {
            float4 wv = *(const float4*)&s_rw[e * HID + k4 * 4];
            acc[e] += xv.x * wv.x + xv.y * wv.y + xv.z * wv.z + xv.w * wv.w;
        }
    }
#pragma unroll
    for (int e = 0; e < NEXP; e++) {
#pragma unroll
        for (int o = 16; o > 0; o >>= 1)
            acc[e] += __shfl_xor_sync(0xffffffffu, acc[e], o);
    }

    if (lane == 0) {
#pragma unroll
        for (int e = 0; e < NEXP; e++) acc[e] += rb[e];
        int b0 = 0; float v0 = acc[0];
#pragma unroll
        for (int e = 1; e < NEXP; e++) { if (acc[e] > v0) { v0 = acc[e]; b0 = e; } }
        int b1 = -1; float v1 = -3.4e38f;
#pragma unroll
        for (int e = 0; e < NEXP; e++) {
            if (e != b0 && acc[e] > v1) { v1 = acc[e]; b1 = e; }
        }
        float den = 0.f, ex[NEXP];
#pragma unroll
        for (int e = 0; e < NEXP; e++) { ex[e] = expf(acc[e] - v0); den += ex[e]; }
        float w0 = ex[b0] / den;
        float w1 = ex[b1] / den;

        int a0 = -1, a1 = -1; float aw0 = 0.f, aw1 = 0.f, wn = 0.f;
        if (b0 == NEXP - 1) wn = w0; else { a0 = b0; aw0 = w0; }
        if (b1 == NEXP - 1) wn = w1;
        else { if (a0 < 0) { a0 = b1; aw0 = w1; } else { a1 = b1; aw1 = w1; } }

        g_e01[t] = make_int2(a0, a1);
        g_w01[t] = make_float2(aw0, aw1);
        g_wn[t]  = wn;
    }
}

/* ---------------- capacity: ordered compaction per expert ---------------- */
__global__ __launch_bounds__(256) void capacity_kernel()
{
    int e = blockIdx.x;
    int tid = threadIdx.x;
    int lane = tid & 31, warp = tid >> 5;
    __shared__ int s_base;
    __shared__ int s_wt[8];
    if (tid == 0) s_base = 0;
    __syncthreads();

    for (int c = 0; c < NTOK / 256; c++) {
        int t = c * 256 + tid;
        int2 a = g_e01[t];
        float2 w = g_w01[t];
        int flag = 0; float wt = 0.f;
        if (a.x == e)      { flag = 1; wt = w.x; }
        else if (a.y == e) { flag = 1; wt = w.y; }
        unsigned m = __ballot_sync(0xffffffffu, flag);
        if (lane == 0) s_wt[warp] = __popc(m);
        __syncthreads();
        int base = s_base;
        int off = 0, tot = 0;
#pragma unroll
        for (int i = 0; i < 8; i++) { int v = s_wt[i]; tot += v; if (i < warp) off += v; }
        int pre = __popc(m & ((1u << lane) - 1u));
        int pos = base + off + pre;
        if (flag && pos < CAP) { g_list[e * CAP + pos] = t; g_wl[e * CAP + pos] = wt; }
        __syncthreads();
        if (tid == 0) s_base = base + tot;
    }
    __syncthreads();
    int count = s_base; if (count > CAP) count = CAP;
    for (int i = count + tid; i < CAP; i += 256) { g_list[e * CAP + i] = 0; g_wl[e * CAP + i] = 0.f; }
}

/* -------- fused: out = w_noop * x ; g_xh = fp16(x) ------------------------ */
__global__ __launch_bounds__(256) void init_cvt_kernel(const float* __restrict__ x,
                                                       float* __restrict__ out)
{
    size_t i = (size_t)blockIdx.x * blockDim.x + threadIdx.x;   /* float4 idx */
    float4 v = ((const float4*)x)[i];
    __half2* p = (__half2*)g_xh;
    p[i * 2 + 0] = __floats2half2_rn(v.x, v.y);
    p[i * 2 + 1] = __floats2half2_rn(v.z, v.w);
    float w = g_wn[i >> 8];
    v.x *= w; v.y *= w; v.z *= w; v.w *= w;
    ((float4*)out)[i] = v;
}

/* transpose [R][C] f32 -> [C][R] fp16; one 32x32 tile per block.
   Stores are 8B per lane (half4), conflict-free smem reads. */
__global__ __launch_bounds__(256) void transpose_wi_kernel(const float* __restrict__ Wi)
{
    __shared__ float tile[32][33];
    int e = blockIdx.z;
    const float* ip = Wi + (size_t)e * HID * INTER;
    __half* op = g_Wih + (size_t)e * HID * INTER;
    int c0 = blockIdx.x * 32, r0 = blockIdx.y * 32;
    int tid = threadIdx.x;
    int tx = tid & 31, ty = tid >> 5;
#pragma unroll
    for (int j = 0; j < 32; j += 8)
        tile[ty + j][tx] = ip[(size_t)(r0 + ty + j) * INTER + c0 + tx];
    __syncthreads();
    int orow = tid >> 3;            /* 0..31 : output row (input col)  */
    int oc4  = (tid & 7) << 2;      /* 0..28 : output col (input row)  */
    H4 v;
    v.a = __floats2half2_rn(tile[oc4 + 0][orow], tile[oc4 + 1][orow]);
    v.b = __floats2half2_rn(tile[oc4 + 2][orow], tile[oc4 + 3][orow]);
    *(H4*)&op[(size_t)(c0 + orow) * HID + r0 + oc4] = v;
}

__global__ __launch_bounds__(256) void transpose_wo_kernel(const float* __restrict__ Wo)
{
    __shared__ float tile[32][33];
    int e = blockIdx.z;
    const float* ip = Wo + (size_t)e * INTER * HID;
    __half* op = g_Woh + (size_t)e * INTER * HID;
    int c0 = blockIdx.x * 32, r0 = blockIdx.y * 32;
    int tid = threadIdx.x;
    int tx = tid & 31, ty = tid >> 5;
#pragma unroll
    for (int j = 0; j < 32; j += 8)
        tile[ty + j][tx] = ip[(size_t)(r0 + ty + j) * HID + c0 + tx];
    __syncthreads();
    int orow = tid >> 3;
    int oc4  = (tid & 7) << 2;
    H4 v;
    v.a = __floats2half2_rn(tile[oc4 + 0][orow], tile[oc4 + 1][orow]);
    v.b = __floats2half2_rn(tile[oc4 + 2][orow], tile[oc4 + 3][orow]);
    *(H4*)&op[(size_t)(c0 + orow) * INTER + r0 + oc4] = v;
}

/* ---------------- fp16 GEMM: 128x128 CTA, ldmatrix + mma.m16n8k16 ---------
   8 warps as 2(M) x 4(N), warp tile 64x32 (4 m16 x 4 n8), K-chunk 64,
   3-stage cp.async (2 in flight), 2 CTAs/SM (4 warps/SMSP).
   is_g1 != 0: A = gathered g_xh rows, B = g_Wih; epilogue relu -> g_Hh
   is_g1 == 0: A = g_Hh rows,          B = g_Woh; epilogue weighted atomic -> outp */

#define LOAD_CHUNK(chunk, slot) do {                                              \
    int k0_ = (chunk) * 64;                                                       \
    unsigned sb_ = tile_base + (unsigned)(slot) * STAGE_BYTES;                    \
    for (int t_ = 0; t_ < 4; t_++) {      /* A: 1024 segs of 16B (128 rows) */    \
        int sid_ = t_ * 256 + tid;                                                \
        int row_ = sid_ >> 3; int seg_ = sid_ & 7;                                \
        size_t r_ = is_g1 ? (size_t)s_tok[row_] : (size_t)(a_row0 + row_);        \
        cp_async16(sb_ + sw128((unsigned)(row_ * 128 + seg_ * 16)),               \
                   Ab + r_ * as_ + k0_ + seg_ * 8);                               \
    }                                                                             \
    for (int t_ = 0; t_ < 4; t_++) {      /* B: 1024 segs of 16B (128 rows) */    \
        int sid_ = t_ * 256 + tid;                                                \
        int row_ = sid_ >> 3; int seg_ = sid_ & 7;                                \
        cp_async16(sb_ + 16384u + sw128((unsigned)(row_ * 128 + seg_ * 16)),      \
                   Bb + (size_t)(b_row0 + row_) * bs_ + k0_ + seg_ * 8);          \
    }                                                                             \
} while (0)

__global__ __launch_bounds__(256, 2) void gemm_fp16_kernel(int KT, int is_g1,
                                                           float* __restrict__ outp)
{
    extern __shared__ float dsm[];
    __shared__ int s_tok[128];

    int e = blockIdx.z, bm = blockIdx.y, bn = blockIdx.x;
    int tid = threadIdx.x, wid = tid >> 5, lane = tid & 31;

    unsigned tile_base = (smem_u32(dsm) + 1023u) & ~1023u;

    if (is_g1 && tid < 128) s_tok[tid] = g_list[e * CAP + bm * 128 + tid];

    const __half* Ab; size_t as_;
    const __half* Bb; size_t bs_;
    if (is_g1) { Ab = g_xh;                            as_ = HID;
                 Bb = g_Wih + (size_t)e * INTER * HID; bs_ = HID; }
    else       { Ab = g_Hh  + (size_t)e * CAP * INTER; as_ = INTER;
                 Bb = g_Woh + (size_t)e * HID * INTER; bs_ = INTER; }
    int a_row0 = bm * 128, b_row0 = bn * 128;

    __syncthreads();   /* s_tok visible before first gather load */

    /* prologue: chunks 0,1 into slots 0,1 */
    for (int c = 0; c < STAGES - 1; c++) { LOAD_CHUNK(c, c); cp_commit(); }

    /* warp tiling: wr = M half (64 rows), wc = N quarter (32 cols) */
    int wr = wid & 1, wc = wid >> 1;
    int lrow = lane & 15, lkg = lane >> 4;
    int arowb = wr * 64, bcolb = wc * 32;

    float acc[4][4][4];
#pragma unroll
    for (int mi = 0; mi < 4; mi++)
#pragma unroll
        for (int ni = 0; ni < 4; ni++)
#pragma unroll
            for (int q = 0; q < 4; q++) acc[mi][ni][q] = 0.f;

    for (int i = 0; i < KT; i++) {
        cp_wait_1();
        __syncthreads();            /* chunk i resident; slot of chunk i-1 free */

        int n = i + STAGES - 1;
        if (n < KT) { LOAD_CHUNK(n, n % STAGES); }
        cp_commit();

        unsigned sA = tile_base + (unsigned)(i % STAGES) * STAGE_BYTES;
        unsigned sB = sA + 16384u;

#pragma unroll
        for (int k16 = 0; k16 < 4; k16++) {
            unsigned kb = (unsigned)(k16 * 32 + lkg * 16);
            unsigned af[4][4];
#pragma unroll
            for (int mi = 0; mi < 4; mi++)
                ldm_x4(af[mi], sA + sw128((unsigned)((arowb + mi * 16 + lrow) * 128) + kb));
            unsigned bf[2][4];
#pragma unroll
            for (int nb = 0; nb < 2; nb++)
                ldm_x4(bf[nb], sB + sw128((unsigned)((bcolb + nb * 16 + lrow) * 128) + kb));
#pragma unroll
            for (int mi = 0; mi < 4; mi++) {
                mma16816(acc[mi][0], af[mi], bf[0][0], bf[0][2]);
                mma16816(acc[mi][1], af[mi], bf[0][1], bf[0][3]);
                mma16816(acc[mi][2], af[mi], bf[1][0], bf[1][2]);
                mma16816(acc[mi][3], af[mi], bf[1][1], bf[1][3]);
            }
        }
    }

    /* ---------------- epilogue (acc in registers; no sync needed) ----------
       m16n8 D layout: d0,d1 -> (row lane>>2,   col (lane&3)*2, +1)
                       d2,d3 -> (row lane>>2+8, same cols)                   */
    int rbase = (lane >> 2), cpair = (lane & 3) * 2;

    if (is_g1) {
        __half* He = g_Hh + (size_t)e * CAP * INTER;
#pragma unroll
        for (int mi = 0; mi < 4; mi++) {
            int r0 = a_row0 + arowb + mi * 16 + rbase;
#pragma unroll
            for (int ni = 0; ni < 4; ni++) {
                int gc = bn * 128 + bcolb + ni * 8 + cpair;
                float* d = acc[mi][ni];
                __half2 h0 = __floats2half2_rn(fmaxf(d[0], 0.f), fmaxf(d[1], 0.f));
                __half2 h1 = __floats2half2_rn(fmaxf(d[2], 0.f), fmaxf(d[3], 0.f));
                *(__half2*)&He[(size_t)r0 * INTER + gc]       = h0;
                *(__half2*)&He[(size_t)(r0 + 8) * INTER + gc] = h1;
            }
        }
    } else {
#pragma unroll
        for (int mi = 0; mi < 4; mi++) {
            int r0 = a_row0 + arowb + mi * 16 + rbase;
            int tok0 = g_list[e * CAP + r0];
            float wt0 = g_wl[e * CAP + r0];
            int tok1 = g_list[e * CAP + r0 + 8];
            float wt1 = g_wl[e * CAP + r0 + 8];
#pragma unroll
            for (int ni = 0; ni < 4; ni++) {
                int gc = bn * 128 + bcolb + ni * 8 + cpair;
                float* d = acc[mi][ni];
                atomicAdd(&outp[(size_t)tok0 * HID + gc],     wt0 * d[0]);
                atomicAdd(&outp[(size_t)tok0 * HID + gc + 1], wt0 * d[1]);
                atomicAdd(&outp[(size_t)tok1 * HID + gc],     wt1 * d[2]);
                atomicAdd(&outp[(size_t)tok1 * HID + gc + 1], wt1 * d[3]);
            }
        }
    }
}

/* ---------------- launch --------------------------------------------------- */
extern "C" void kernel_launch(void* const* d_in, const int* in_sizes, int n_in,
                              void* d_out, int out_size)
{
    const float *x = 0, *rw = 0, *rb = 0, *Wi = 0, *Wo = 0;
    for (int i = 0; i < n_in; i++) {
        long long sz = in_sizes[i];
        const float* p = (const float*)d_in[i];
        if (sz == (long long)NTOK * HID)                { x  = p; }
        else if (sz == NEXP * HID)                      { rw = p; }
        else if (sz == NEXP)                            { rb = p; }
        else if (sz == (long long)NEXPC * HID * INTER)  { if (!Wi) Wi = p; else Wo = p; }
    }
    if (!x || !rw || !rb || !Wi || !Wo) {
        x  = (const float*)d_in[0];
        rw = (const float*)d_in[1];
        rb = (const float*)d_in[2];
        Wi = (const float*)d_in[3];
        Wo = (const float*)d_in[4];
    }
    float* out = (float*)d_out;

    static cudaStream_t s2 = 0, s3 = 0;
    static cudaEvent_t evRoot = 0, evT1 = 0, evT2 = 0;
    static bool once = false;
    if (!once) {
        cudaFuncSetAttribute(gemm_fp16_kernel, cudaFuncAttributeMaxDynamicSharedMemorySize,
                             GEMM_SMEM);
        cudaStreamCreateWithFlags(&s2, cudaStreamNonBlocking);
        cudaStreamCreateWithFlags(&s3, cudaStreamNonBlocking);
        cudaEventCreateWithFlags(&evRoot, cudaEventDisableTiming);
        cudaEventCreateWithFlags(&evT1, cudaEventDisableTiming);
        cudaEventCreateWithFlags(&evT2, cudaEventDisableTiming);
        once = true;
    }

    /* fork: transposes run on side streams, concurrent with router chain */
    cudaEventRecord(evRoot, 0);
    cudaStreamWaitEvent(s2, evRoot, 0);
    cudaStreamWaitEvent(s3, evRoot, 0);

    transpose_wi_kernel<<<dim3(INTER / 32, HID / 32, NEXPC), 256, 0, s2>>>(Wi);
    transpose_wo_kernel<<<dim3(HID / 32, INTER / 32, NEXPC), 256, 0, s3>>>(Wo);
    cudaEventRecord(evT1, s2);
    cudaEventRecord(evT2, s3);

    router_kernel<<<NTOK / 8, 256>>>(x, rw, rb);
    capacity_kernel<<<NEXPC, 256>>>();
    init_cvt_kernel<<<(NTOK * HID / 4) / 256, 256>>>(x, out);

    /* gemm1 needs Wi^T only */
    cudaStreamWaitEvent(0, evT1, 0);
    gemm_fp16_kernel<<<dim3(INTER / 128, CAP / 128, NEXPC), 256, GEMM_SMEM>>>(HID / 64, 1, 0);

    /* gemm2 additionally needs Wo^T */
    cudaStreamWaitEvent(0, evT2, 0);
    gemm_fp16_kernel<<<dim3(HID / 128, CAP / 128, NEXPC), 256, GEMM_SMEM>>>(INTER / 64, 0, out);
}

// round 17
// speedup vs baseline: 1.0523x; 1.0523x over previous
#include <cuda_runtime.h>
#include <cuda_fp16.h>
#include <stdint.h>
#include <math.h>

#define NTOK  8192
#define HID   1024
#define INTER 4096
#define NEXP  8
#define NEXPC 7
#define CAP   1024

#define STAGES      3
#define STAGE_BYTES 32768           /* A 16KB (128 rows) + B 16KB (128 rows) */
#define GEMM_SMEM   (STAGES * STAGE_BYTES + 1024)

/* ---------------- device scratch (static: no allocations allowed) -------- */
__device__ int2   g_e01[NTOK];
__device__ float2 g_w01[NTOK];
__device__ int    g_list[NEXPC * CAP];
__device__ float  g_wl[NEXPC * CAP];
__device__ __half g_xh[(size_t)NTOK * HID];             /* fp16 x            */
__device__ __half g_Wih[(size_t)NEXPC * INTER * HID];   /* Wi^T [e][n][k]    */
__device__ __half g_Woh[(size_t)NEXPC * HID * INTER];   /* Wo^T [e][n][k]    */
__device__ __half g_Hh[(size_t)NEXPC * CAP * INTER];    /* fp16 H            */

struct __align__(8) H4 { __half2 a, b; };

/* ---------------- helpers -------------------------------------------------- */
__device__ __forceinline__ unsigned smem_u32(const void* p) {
    return (unsigned)__cvta_generic_to_shared(p);
}
__device__ __forceinline__ unsigned sw128(unsigned x) { return x ^ ((x >> 3) & 0x70u); }

__device__ __forceinline__ void cp_async16(unsigned sa, const void* g) {
    asm volatile("cp.async.cg.shared.global [%0], [%1], 16;" :: "r"(sa), "l"(g));
}
__device__ __forceinline__ void cp_commit() {
    asm volatile("cp.async.commit_group;");
}
__device__ __forceinline__ void cp_wait_1() {
    asm volatile("cp.async.wait_group 1;");
}

__device__ __forceinline__ void ldm_x4(unsigned* r, unsigned addr) {
    asm volatile("ldmatrix.sync.aligned.m8n8.x4.shared.b16 {%0, %1, %2, %3}, [%4];"
                 : "=r"(r[0]), "=r"(r[1]), "=r"(r[2]), "=r"(r[3]) : "r"(addr));
}
__device__ __forceinline__ void mma16816(float* d, const unsigned* a,
                                         unsigned b0, unsigned b1) {
    asm volatile(
        "mma.sync.aligned.m16n8k16.row.col.f32.f16.f16.f32 "
        "{%0, %1, %2, %3}, {%4, %5, %6, %7}, {%8, %9}, {%0, %1, %2, %3};"
        : "+f"(d[0]), "+f"(d[1]), "+f"(d[2]), "+f"(d[3])
        : "r"(a[0]), "r"(a[1]), "r"(a[2]), "r"(a[3]), "r"(b0), "r"(b1));
}

/* ---- router fused with init/cvt: logits->softmax->top2, out=wn*x, xh=fp16(x) */
__global__ __launch_bounds__(256) void router_kernel(const float* __restrict__ x,
                                                     const float* __restrict__ rw,
                                                     const float* __restrict__ rb,
                                                     float* __restrict__ out)
{
    __shared__ __align__(16) float s_rw[NEXP * HID];
    int tid = threadIdx.x;
    for (int i = tid * 4; i < NEXP * HID; i += 256 * 4)
        *(float4*)&s_rw[i] = *(const float4*)&rw[i];
    __syncthreads();

    int lane = tid & 31;
    int warp = tid >> 5;
    int t = blockIdx.x * 8 + warp;

    float acc[NEXP];
#pragma unroll
    for (int e = 0; e < NEXP; e++) acc[e] = 0.f;

    const float4* xr = (const float4*)(x + (size_t)t * HID);
    float4 xv[8];
#pragma unroll
    for (int i = 0; i < 8; i++) {
        int k4 = lane + i * 32;
        xv[i] = xr[k4];
#pragma unroll
        for (int e = 0; e < NEXP; e++) {
            float4 wv = *(const float4*)&s_rw[e * HID + k4 * 4];
            acc[e] += xv[i].x * wv.x + xv[i].y * wv.y + xv[i].z * wv.z + xv[i].w * wv.w;
        }
    }
#pragma unroll
    for (int e = 0; e < NEXP; e++) {
#pragma unroll
        for (int o = 16; o > 0; o >>= 1)
            acc[e] += __shfl_xor_sync(0xffffffffu, acc[e], o);
    }

    float wn = 0.f;
    if (lane == 0) {
#pragma unroll
        for (int e = 0; e < NEXP; e++) acc[e] += rb[e];
        int b0 = 0; float v0 = acc[0];
#pragma unroll
        for (int e = 1; e < NEXP; e++) { if (acc[e] > v0) { v0 = acc[e]; b0 = e; } }
        int b1 = -1; float v1 = -3.4e38f;
#pragma unroll
        for (int e = 0; e < NEXP; e++) {
            if (e != b0 && acc[e] > v1) { v1 = acc[e]; b1 = e; }
        }
        float den = 0.f, ex[NEXP];
#pragma unroll
        for (int e = 0; e < NEXP; e++) { ex[e] = expf(acc[e] - v0); den += ex[e]; }
        float w0 = ex[b0] / den;
        float w1 = ex[b1] / den;

        int a0 = -1, a1 = -1; float aw0 = 0.f, aw1 = 0.f;
        if (b0 == NEXP - 1) wn = w0; else { a0 = b0; aw0 = w0; }
        if (b1 == NEXP - 1) wn = w1;
        else { if (a0 < 0) { a0 = b1; aw0 = w1; } else { a1 = b1; aw1 = w1; } }

        g_e01[t] = make_int2(a0, a1);
        g_w01[t] = make_float2(aw0, aw1);
    }
    wn = __shfl_sync(0xffffffffu, wn, 0);

    /* write fp16 copy of x and the noop-weighted output from registers */
    __half2* xhp = (__half2*)(g_xh + (size_t)t * HID);
    float4* op = (float4*)(out + (size_t)t * HID);
#pragma unroll
    for (int i = 0; i < 8; i++) {
        int k4 = lane + i * 32;
        xhp[k4 * 2 + 0] = __floats2half2_rn(xv[i].x, xv[i].y);
        xhp[k4 * 2 + 1] = __floats2half2_rn(xv[i].z, xv[i].w);
        float4 v = xv[i];
        v.x *= wn; v.y *= wn; v.z *= wn; v.w *= wn;
        op[k4] = v;
    }
}

/* -------- capacity: parallel stable compaction. grid (32 chunks, 7 experts) */
__global__ __launch_bounds__(256) void capacity_kernel()
{
    int chunk = blockIdx.x;            /* 0..31 */
    int e     = blockIdx.y;            /* 0..6  */
    int tid = threadIdx.x;
    int lane = tid & 31, warp = tid >> 5;
    __shared__ int s_red[8];
    __shared__ int s_wt[8];

    /* count matches in all chunks before mine (parallel over threads) */
    int cnt = 0;
    for (int c = 0; c < chunk; c++) {
        int2 a = g_e01[c * 256 + tid];
        if (a.x == e || a.y == e) cnt++;
    }
#pragma unroll
    for (int o = 16; o > 0; o >>= 1) cnt += __shfl_xor_sync(0xffffffffu, cnt, o);
    if (lane == 0) s_red[warp] = cnt;
    __syncthreads();
    int base = 0;
#pragma unroll
    for (int i = 0; i < 8; i++) base += s_red[i];

    /* my chunk: stable ballot-scan */
    int t = chunk * 256 + tid;
    int2 a = g_e01[t];
    float2 w = g_w01[t];
    int flag = 0; float wt = 0.f;
    if (a.x == e)      { flag = 1; wt = w.x; }
    else if (a.y == e) { flag = 1; wt = w.y; }
    unsigned m = __ballot_sync(0xffffffffu, flag);
    if (lane == 0) s_wt[warp] = __popc(m);
    __syncthreads();
    int off = 0, tot = 0;
#pragma unroll
    for (int i = 0; i < 8; i++) { int v = s_wt[i]; tot += v; if (i < warp) off += v; }
    int pre = __popc(m & ((1u << lane) - 1u));
    int pos = base + off + pre;
    if (flag && pos < CAP) { g_list[e * CAP + pos] = t; g_wl[e * CAP + pos] = wt; }

    /* last chunk's block knows the expert total -> fill padding */
    if (chunk == 31) {
        int count = base + tot; if (count > CAP) count = CAP;
        for (int i = count + tid; i < CAP; i += 256) {
            g_list[e * CAP + i] = 0; g_wl[e * CAP + i] = 0.f;
        }
    }
}

/* transpose [R][C] f32 -> [C][R] fp16; one 32x32 tile per block. */
__global__ __launch_bounds__(256) void transpose_wi_kernel(const float* __restrict__ Wi)
{
    __shared__ float tile[32][33];
    int e = blockIdx.z;
    const float* ip = Wi + (size_t)e * HID * INTER;
    __half* op = g_Wih + (size_t)e * HID * INTER;
    int c0 = blockIdx.x * 32, r0 = blockIdx.y * 32;
    int tid = threadIdx.x;
    int tx = tid & 31, ty = tid >> 5;
#pragma unroll
    for (int j = 0; j < 32; j += 8)
        tile[ty + j][tx] = ip[(size_t)(r0 + ty + j) * INTER + c0 + tx];
    __syncthreads();
    int orow = tid >> 3;
    int oc4  = (tid & 7) << 2;
    H4 v;
    v.a = __floats2half2_rn(tile[oc4 + 0][orow], tile[oc4 + 1][orow]);
    v.b = __floats2half2_rn(tile[oc4 + 2][orow], tile[oc4 + 3][orow]);
    *(H4*)&op[(size_t)(c0 + orow) * HID + r0 + oc4] = v;
}

__global__ __launch_bounds__(256) void transpose_wo_kernel(const float* __restrict__ Wo)
{
    __shared__ float tile[32][33];
    int e = blockIdx.z;
    const float* ip = Wo + (size_t)e * INTER * HID;
    __half* op = g_Woh + (size_t)e * INTER * HID;
    int c0 = blockIdx.x * 32, r0 = blockIdx.y * 32;
    int tid = threadIdx.x;
    int tx = tid & 31, ty = tid >> 5;
#pragma unroll
    for (int j = 0; j < 32; j += 8)
        tile[ty + j][tx] = ip[(size_t)(r0 + ty + j) * HID + c0 + tx];
    __syncthreads();
    int orow = tid >> 3;
    int oc4  = (tid & 7) << 2;
    H4 v;
    v.a = __floats2half2_rn(tile[oc4 + 0][orow], tile[oc4 + 1][orow]);
    v.b = __floats2half2_rn(tile[oc4 + 2][orow], tile[oc4 + 3][orow]);
    *(H4*)&op[(size_t)(c0 + orow) * INTER + r0 + oc4] = v;
}

/* ---------------- fp16 GEMM: 128x128 CTA, ldmatrix + mma.m16n8k16 ---------
   8 warps as 2(M) x 4(N), warp tile 64x32 (4 m16 x 4 n8), K-chunk 64,
   3-stage cp.async (2 in flight), 2 CTAs/SM (4 warps/SMSP). */

#define LOAD_CHUNK(chunk, slot) do {                                              \
    int k0_ = (chunk) * 64;                                                       \
    unsigned sb_ = tile_base + (unsigned)(slot) * STAGE_BYTES;                    \
    for (int t_ = 0; t_ < 4; t_++) {      /* A: 1024 segs of 16B (128 rows) */    \
        int sid_ = t_ * 256 + tid;                                                \
        int row_ = sid_ >> 3; int seg_ = sid_ & 7;                                \
        size_t r_ = is_g1 ? (size_t)s_tok[row_] : (size_t)(a_row0 + row_);        \
        cp_async16(sb_ + sw128((unsigned)(row_ * 128 + seg_ * 16)),               \
                   Ab + r_ * as_ + k0_ + seg_ * 8);                               \
    }                                                                             \
    for (int t_ = 0; t_ < 4; t_++) {      /* B: 1024 segs of 16B (128 rows) */    \
        int sid_ = t_ * 256 + tid;                                                \
        int row_ = sid_ >> 3; int seg_ = sid_ & 7;                                \
        cp_async16(sb_ + 16384u + sw128((unsigned)(row_ * 128 + seg_ * 16)),      \
                   Bb + (size_t)(b_row0 + row_) * bs_ + k0_ + seg_ * 8);          \
    }                                                                             \
} while (0)

__global__ __launch_bounds__(256, 2) void gemm_fp16_kernel(int KT, int is_g1,
                                                           float* __restrict__ outp)
{
    extern __shared__ float dsm[];
    __shared__ int s_tok[128];

    int e = blockIdx.z, bm = blockIdx.y, bn = blockIdx.x;
    int tid = threadIdx.x, wid = tid >> 5, lane = tid & 31;

    unsigned tile_base = (smem_u32(dsm) + 1023u) & ~1023u;

    if (is_g1 && tid < 128) s_tok[tid] = g_list[e * CAP + bm * 128 + tid];

    const __half* Ab; size_t as_;
    const __half* Bb; size_t bs_;
    if (is_g1) { Ab = g_xh;                            as_ = HID;
                 Bb = g_Wih + (size_t)e * INTER * HID; bs_ = HID; }
    else       { Ab = g_Hh  + (size_t)e * CAP * INTER; as_ = INTER;
                 Bb = g_Woh + (size_t)e * HID * INTER; bs_ = INTER; }
    int a_row0 = bm * 128, b_row0 = bn * 128;

    __syncthreads();   /* s_tok visible before first gather load */

    for (int c = 0; c < STAGES - 1; c++) { LOAD_CHUNK(c, c); cp_commit(); }

    int wr = wid & 1, wc = wid >> 1;
    int lrow = lane & 15, lkg = lane >> 4;
    int arowb = wr * 64, bcolb = wc * 32;

    float acc[4][4][4];
#pragma unroll
    for (int mi = 0; mi < 4; mi++)
#pragma unroll
        for (int ni = 0; ni < 4; ni++)
#pragma unroll
            for (int q = 0; q < 4; q++) acc[mi][ni][q] = 0.f;

    for (int i = 0; i < KT; i++) {
        cp_wait_1();
        __syncthreads();

        int n = i + STAGES - 1;
        if (n < KT) { LOAD_CHUNK(n, n % STAGES); }
        cp_commit();

        unsigned sA = tile_base + (unsigned)(i % STAGES) * STAGE_BYTES;
        unsigned sB = sA + 16384u;

#pragma unroll
        for (int k16 = 0; k16 < 4; k16++) {
            unsigned kb = (unsigned)(k16 * 32 + lkg * 16);
            unsigned af[4][4];
#pragma unroll
            for (int mi = 0; mi < 4; mi++)
                ldm_x4(af[mi], sA + sw128((unsigned)((arowb + mi * 16 + lrow) * 128) + kb));
            unsigned bf[2][4];
#pragma unroll
            for (int nb = 0; nb < 2; nb++)
                ldm_x4(bf[nb], sB + sw128((unsigned)((bcolb + nb * 16 + lrow) * 128) + kb));
#pragma unroll
            for (int mi = 0; mi < 4; mi++) {
                mma16816(acc[mi][0], af[mi], bf[0][0], bf[0][2]);
                mma16816(acc[mi][1], af[mi], bf[0][1], bf[0][3]);
                mma16816(acc[mi][2], af[mi], bf[1][0], bf[1][2]);
                mma16816(acc[mi][3], af[mi], bf[1][1], bf[1][3]);
            }
        }
    }

    int rbase = (lane >> 2), cpair = (lane & 3) * 2;

    if (is_g1) {
        __half* He = g_Hh + (size_t)e * CAP * INTER;
#pragma unroll
        for (int mi = 0; mi < 4; mi++) {
            int r0 = a_row0 + arowb + mi * 16 + rbase;
#pragma unroll
            for (int ni = 0; ni < 4; ni++) {
                int gc = bn * 128 + bcolb + ni * 8 + cpair;
                float* d = acc[mi][ni];
                __half2 h0 = __floats2half2_rn(fmaxf(d[0], 0.f), fmaxf(d[1], 0.f));
                __half2 h1 = __floats2half2_rn(fmaxf(d[2], 0.f), fmaxf(d[3], 0.f));
                *(__half2*)&He[(size_t)r0 * INTER + gc]       = h0;
                *(__half2*)&He[(size_t)(r0 + 8) * INTER + gc] = h1;
            }
        }
    } else {
#pragma unroll
        for (int mi = 0; mi < 4; mi++) {
            int r0 = a_row0 + arowb + mi * 16 + rbase;
            int tok0 = g_list[e * CAP + r0];
            float wt0 = g_wl[e * CAP + r0];
            int tok1 = g_list[e * CAP + r0 + 8];
            float wt1 = g_wl[e * CAP + r0 + 8];
#pragma unroll
            for (int ni = 0; ni < 4; ni++) {
                int gc = bn * 128 + bcolb + ni * 8 + cpair;
                float* d = acc[mi][ni];
                atomicAdd(&outp[(size_t)tok0 * HID + gc],     wt0 * d[0]);
                atomicAdd(&outp[(size_t)tok0 * HID + gc + 1], wt0 * d[1]);
                atomicAdd(&outp[(size_t)tok1 * HID + gc],     wt1 * d[2]);
                atomicAdd(&outp[(size_t)tok1 * HID + gc + 1], wt1 * d[3]);
            }
        }
    }
}

/* ---------------- launch --------------------------------------------------- */
extern "C" void kernel_launch(void* const* d_in, const int* in_sizes, int n_in,
                              void* d_out, int out_size)
{
    const float *x = 0, *rw = 0, *rb = 0, *Wi = 0, *Wo = 0;
    for (int i = 0; i < n_in; i++) {
        long long sz = in_sizes[i];
        const float* p = (const float*)d_in[i];
        if (sz == (long long)NTOK * HID)                { x  = p; }
        else if (sz == NEXP * HID)                      { rw = p; }
        else if (sz == NEXP)                            { rb = p; }
        else if (sz == (long long)NEXPC * HID * INTER)  { if (!Wi) Wi = p; else Wo = p; }
    }
    if (!x || !rw || !rb || !Wi || !Wo) {
        x  = (const float*)d_in[0];
        rw = (const float*)d_in[1];
        rb = (const float*)d_in[2];
        Wi = (const float*)d_in[3];
        Wo = (const float*)d_in[4];
    }
    float* out = (float*)d_out;

    static bool once = false;
    if (!once) {
        cudaFuncSetAttribute(gemm_fp16_kernel, cudaFuncAttributeMaxDynamicSharedMemorySize,
                             GEMM_SMEM);
        once = true;
    }

    /* order chosen so gemm1 is this module's 4th launch (ncu -s 5 captures it) */
    router_kernel<<<NTOK / 8, 256>>>(x, rw, rb, out);
    capacity_kernel<<<dim3(32, NEXPC), 256>>>();
    transpose_wi_kernel<<<dim3(INTER / 32, HID / 32, NEXPC), 256>>>(Wi);
    gemm_fp16_kernel<<<dim3(INTER / 128, CAP / 128, NEXPC), 256, GEMM_SMEM>>>(HID / 64, 1, 0);
    transpose_wo_kernel<<<dim3(HID / 32, INTER / 32, NEXPC), 256>>>(Wo);
    gemm_fp16_kernel<<<dim3(HID / 128, CAP / 128, NEXPC), 256, GEMM_SMEM>>>(INTER / 64, 0, out);
}